// round 8
// baseline (speedup 1.0000x reference)
#include <cuda_runtime.h>
#include <cuda_fp16.h>
#include <cstdint>

// ============================================================
// Y[8192,4096] = X[8192,4096] @ dequant4(Wq,Wn)^T + bias
// Prepass: X f32->f16, W int4->f16.  Main: f16 GEMM (mma.sync
// m16n8k16, fp32 accum), cp.async 3-stage, SW128 swizzle.
// ============================================================
#define M_DIM 8192
#define N_DIM 4096
#define K_DIM 4096

__device__ __half g_Xh[(size_t)M_DIM * K_DIM];   // 64 MiB scratch
__device__ __half g_Wh[(size_t)N_DIM * K_DIM];   // 32 MiB scratch

// ---------------- prepass kernels ----------------
__global__ void __launch_bounds__(256)
conv_x_kernel(const float* __restrict__ X) {
    size_t i = ((size_t)blockIdx.x * 256 + threadIdx.x) * 8;
    float4 f0 = *reinterpret_cast<const float4*>(X + i);
    float4 f1 = *reinterpret_cast<const float4*>(X + i + 4);
    __half2 h[4];
    h[0] = __floats2half2_rn(f0.x, f0.y);
    h[1] = __floats2half2_rn(f0.z, f0.w);
    h[2] = __floats2half2_rn(f1.x, f1.y);
    h[3] = __floats2half2_rn(f1.z, f1.w);
    *reinterpret_cast<uint4*>(g_Xh + i) = *reinterpret_cast<const uint4*>(h);
}

__global__ void __launch_bounds__(256)
dequant_w_kernel(const int* __restrict__ Wq, const float* __restrict__ Wn) {
    size_t g = (size_t)blockIdx.x * 256 + threadIdx.x;   // group id, 1M groups
    const int4* gp = reinterpret_cast<const int4*>(Wq + g * 8);
    int4 w0 = gp[0], w1 = gp[1];
    float nf = Wn[g];
    float s = nf * (2.0f / 15.0f);
    int v[8] = {w0.x, w0.y, w0.z, w0.w, w1.x, w1.y, w1.z, w1.w};
    __half2 o[8];
    #pragma unroll
    for (int i = 0; i < 8; ++i) {
        float f0 = fmaf((float)(v[i] & 15),        s, -nf);  // low nibble = even k
        float f1 = fmaf((float)((v[i] >> 4) & 15), s, -nf);  // high nibble = odd k
        o[i] = __floats2half2_rn(f0, f1);
    }
    uint4* dst = reinterpret_cast<uint4*>(g_Wh + g * 16);
    dst[0] = reinterpret_cast<const uint4*>(o)[0];
    dst[1] = reinterpret_cast<const uint4*>(o)[1];
}

// ---------------- main GEMM ----------------
#define BM 128
#define BN 128
#define BK 64
#define NT 256
#define NITER (K_DIM / BK)            // 64
#define STAGES 3
#define A_BYTES (BM * BK * 2)         // 16384
#define B_BYTES (BN * BK * 2)         // 16384
#define STAGE_BYTES (A_BYTES + B_BYTES)
#define SMEM_TOTAL (STAGES * STAGE_BYTES)  // 98304

__device__ __forceinline__ uint32_t sw128(uint32_t off) {   // 128B rows
    return off ^ ((off >> 3) & 0x70);
}

__device__ __forceinline__ uint32_t smem_u32(const void* p) {
    uint32_t a;
    asm("{ .reg .u64 t; cvta.to.shared.u64 t, %1; cvt.u32.u64 %0, t; }" : "=r"(a) : "l"(p));
    return a;
}

__device__ __forceinline__ void cp16(uint32_t dst, const void* src) {
    asm volatile("cp.async.cg.shared.global [%0], [%1], 16;\n" :: "r"(dst), "l"(src));
}

__device__ __forceinline__ void ldsm_x4(uint32_t r[4], uint32_t addr) {
    asm volatile("ldmatrix.sync.aligned.m8n8.x4.shared.b16 {%0,%1,%2,%3}, [%4];"
                 : "=r"(r[0]), "=r"(r[1]), "=r"(r[2]), "=r"(r[3]) : "r"(addr));
}

__device__ __forceinline__ void mma_f16(float c[4], const uint32_t a[4], const uint32_t b[2]) {
    asm volatile(
        "mma.sync.aligned.m16n8k16.row.col.f32.f16.f16.f32 "
        "{%0,%1,%2,%3}, {%4,%5,%6,%7}, {%8,%9}, {%0,%1,%2,%3};\n"
        : "+f"(c[0]), "+f"(c[1]), "+f"(c[2]), "+f"(c[3])
        : "r"(a[0]), "r"(a[1]), "r"(a[2]), "r"(a[3]), "r"(b[0]), "r"(b[1]));
}

__global__ void __launch_bounds__(NT, 2)
gemm_f16_kernel(const float* __restrict__ bias, float* __restrict__ Y)
{
    extern __shared__ char smem[];
    const uint32_t smem_base = smem_u32(smem);
    const int tid  = threadIdx.x;
    const int warp = tid >> 5;
    const int lane = tid & 31;
    const int lg   = lane >> 2;
    const int lq   = lane & 3;
    const int wm   = (warp >> 1) * 32;   // 4 warps in M
    const int wn   = (warp & 1) * 64;    // 2 warps in N
    const int bm   = blockIdx.y * BM;
    const int bn   = blockIdx.x * BN;

    float c[2][8][4];
    #pragma unroll
    for (int mi = 0; mi < 2; ++mi)
        #pragma unroll
        for (int ni = 0; ni < 8; ++ni)
            #pragma unroll
            for (int j = 0; j < 4; ++j) c[mi][ni][j] = 0.0f;

    // per-thread load roles: 1024 16B chunks per operand tile, 4 per thread
    auto stage_load = [&](int st, int it) {
        const int k0 = it * BK;
        const uint32_t abase = smem_base + st * STAGE_BYTES;
        const uint32_t bbase = abase + A_BYTES;
        #pragma unroll
        for (int j = 0; j < 4; ++j) {
            int ch = tid + j * NT;           // 0..1023
            int row = ch >> 3, seg = ch & 7; // row, 16B segment
            const __half* sa = g_Xh + (size_t)(bm + row) * K_DIM + k0 + seg * 8;
            cp16(abase + sw128((uint32_t)(row * 128 + seg * 16)), sa);
            const __half* sb = g_Wh + (size_t)(bn + row) * K_DIM + k0 + seg * 8;
            cp16(bbase + sw128((uint32_t)(row * 128 + seg * 16)), sb);
        }
    };

    auto compute = [&](int st) {
        const uint32_t abase = smem_base + st * STAGE_BYTES;
        const uint32_t bbase = abase + A_BYTES;
        #pragma unroll
        for (int ks = 0; ks < 4; ++ks) {     // four k16 steps per BK=64
            uint32_t a[2][4], b[8][2];
            #pragma unroll
            for (int mi = 0; mi < 2; ++mi) {
                int row = wm + mi * 16 + (lane & 15);
                int colh = ks * 16 + ((lane >> 4) << 3);
                ldsm_x4(a[mi], abase + sw128((uint32_t)(row * 128 + colh * 2)));
            }
            #pragma unroll
            for (int nj = 0; nj < 4; ++nj) {
                int row = wn + nj * 16 + ((lane >> 4) << 3) + (lane & 7);
                int colh = ks * 16 + ((lane >> 3) & 1) * 8;
                uint32_t r[4];
                ldsm_x4(r, bbase + sw128((uint32_t)(row * 128 + colh * 2)));
                b[2 * nj][0] = r[0];     b[2 * nj][1] = r[1];
                b[2 * nj + 1][0] = r[2]; b[2 * nj + 1][1] = r[3];
            }
            #pragma unroll
            for (int mi = 0; mi < 2; ++mi)
                #pragma unroll
                for (int ni = 0; ni < 8; ++ni)
                    mma_f16(c[mi][ni], a[mi], b[ni]);
        }
    };

    // ---- prologue: stages 0,1 in flight ----
    stage_load(0, 0);
    asm volatile("cp.async.commit_group;\n");
    stage_load(1, 1);
    asm volatile("cp.async.commit_group;\n");

    for (int it = 0; it < NITER; ++it) {
        asm volatile("cp.async.wait_group 1;\n");   // stage `it` landed
        __syncthreads();                            // all warps done with stage (it-1)
        const int nit = it + 2;
        if (nit < NITER) stage_load(nit % STAGES, nit);
        asm volatile("cp.async.commit_group;\n");   // keep group count uniform
        compute(it % STAGES);
    }

    // ---- epilogue: bias + fp32 store ----
    #pragma unroll
    for (int ni = 0; ni < 8; ++ni) {
        int coln = bn + wn + ni * 8 + 2 * lq;
        float2 bv = *reinterpret_cast<const float2*>(bias + coln);
        #pragma unroll
        for (int mi = 0; mi < 2; ++mi) {
            int r = bm + wm + mi * 16 + lg;
            float2 v0 = make_float2(c[mi][ni][0] + bv.x, c[mi][ni][1] + bv.y);
            float2 v1 = make_float2(c[mi][ni][2] + bv.x, c[mi][ni][3] + bv.y);
            *reinterpret_cast<float2*>(Y + (size_t)r * N_DIM + coln) = v0;
            *reinterpret_cast<float2*>(Y + (size_t)(r + 8) * N_DIM + coln) = v1;
        }
    }
}

extern "C" void kernel_launch(void* const* d_in, const int* in_sizes, int n_in,
                              void* d_out, int out_size) {
    const float* X    = (const float*)d_in[0];
    const int*   Wq   = (const int*)d_in[1];
    const float* Wn   = (const float*)d_in[2];   // fp16 widened to fp32 by harness
    const float* bias = (const float*)d_in[3];
    float*       Y    = (float*)d_out;

    // prepass
    conv_x_kernel<<<(int)(((size_t)M_DIM * K_DIM / 8) / 256), 256>>>(X);
    dequant_w_kernel<<<(int)(((size_t)N_DIM * K_DIM / 16) / 256), 256>>>(Wq, Wn);

    // main GEMM
    cudaFuncSetAttribute(gemm_f16_kernel,
                         cudaFuncAttributeMaxDynamicSharedMemorySize, SMEM_TOTAL);
    dim3 grid(N_DIM / BN, M_DIM / BM);   // (32, 64) — N fastest: W stays L2-resident
    gemm_f16_kernel<<<grid, NT, SMEM_TOTAL>>>(bias, Y);
}

// round 9
// speedup vs baseline: 1.0006x; 1.0006x over previous
#include <cuda_runtime.h>
#include <cuda_fp16.h>
#include <cstdint>

// ============================================================
// Y[8192,4096] = X[8192,4096] @ dequant4(Wq,Wn)^T + bias
// Prepass: X f32->f16, W int4->f16.  Main: f16 GEMM (mma.sync
// m16n8k16, fp32 accum), cp.async 3-stage, SW128 swizzle.
// ============================================================
#define M_DIM 8192
#define N_DIM 4096
#define K_DIM 4096

__device__ __half g_Xh[(size_t)M_DIM * K_DIM];   // 64 MiB scratch
__device__ __half g_Wh[(size_t)N_DIM * K_DIM];   // 32 MiB scratch

// ---------------- prepass kernels ----------------
__global__ void __launch_bounds__(256)
conv_x_kernel(const float* __restrict__ X) {
    size_t i = ((size_t)blockIdx.x * 256 + threadIdx.x) * 8;
    float4 f0 = *reinterpret_cast<const float4*>(X + i);
    float4 f1 = *reinterpret_cast<const float4*>(X + i + 4);
    __half2 h[4];
    h[0] = __floats2half2_rn(f0.x, f0.y);
    h[1] = __floats2half2_rn(f0.z, f0.w);
    h[2] = __floats2half2_rn(f1.x, f1.y);
    h[3] = __floats2half2_rn(f1.z, f1.w);
    *reinterpret_cast<uint4*>(g_Xh + i) = *reinterpret_cast<const uint4*>(h);
}

__global__ void __launch_bounds__(256)
dequant_w_kernel(const int* __restrict__ Wq, const float* __restrict__ Wn) {
    size_t g = (size_t)blockIdx.x * 256 + threadIdx.x;   // group id, 1M groups
    const int4* gp = reinterpret_cast<const int4*>(Wq + g * 8);
    int4 w0 = gp[0], w1 = gp[1];
    float nf = Wn[g];
    float s = nf * (2.0f / 15.0f);
    int v[8] = {w0.x, w0.y, w0.z, w0.w, w1.x, w1.y, w1.z, w1.w};
    __half2 o[8];
    #pragma unroll
    for (int i = 0; i < 8; ++i) {
        float f0 = fmaf((float)(v[i] & 15),        s, -nf);  // low nibble = even k
        float f1 = fmaf((float)((v[i] >> 4) & 15), s, -nf);  // high nibble = odd k
        o[i] = __floats2half2_rn(f0, f1);
    }
    uint4* dst = reinterpret_cast<uint4*>(g_Wh + g * 16);
    dst[0] = reinterpret_cast<const uint4*>(o)[0];
    dst[1] = reinterpret_cast<const uint4*>(o)[1];
}

// ---------------- main GEMM ----------------
#define BM 128
#define BN 128
#define BK 64
#define NT 256
#define NITER (K_DIM / BK)            // 64
#define STAGES 3
#define A_BYTES (BM * BK * 2)         // 16384
#define B_BYTES (BN * BK * 2)         // 16384
#define STAGE_BYTES (A_BYTES + B_BYTES)
#define SMEM_TOTAL (STAGES * STAGE_BYTES)  // 98304

__device__ __forceinline__ uint32_t sw128(uint32_t off) {   // 128B rows
    return off ^ ((off >> 3) & 0x70);
}

__device__ __forceinline__ uint32_t smem_u32(const void* p) {
    uint32_t a;
    asm("{ .reg .u64 t; cvta.to.shared.u64 t, %1; cvt.u32.u64 %0, t; }" : "=r"(a) : "l"(p));
    return a;
}

__device__ __forceinline__ void cp16(uint32_t dst, const void* src) {
    asm volatile("cp.async.cg.shared.global [%0], [%1], 16;\n" :: "r"(dst), "l"(src));
}

__device__ __forceinline__ void ldsm_x4(uint32_t r[4], uint32_t addr) {
    asm volatile("ldmatrix.sync.aligned.m8n8.x4.shared.b16 {%0,%1,%2,%3}, [%4];"
                 : "=r"(r[0]), "=r"(r[1]), "=r"(r[2]), "=r"(r[3]) : "r"(addr));
}

__device__ __forceinline__ void mma_f16(float c[4], const uint32_t a[4], const uint32_t b[2]) {
    asm volatile(
        "mma.sync.aligned.m16n8k16.row.col.f32.f16.f16.f32 "
        "{%0,%1,%2,%3}, {%4,%5,%6,%7}, {%8,%9}, {%0,%1,%2,%3};\n"
        : "+f"(c[0]), "+f"(c[1]), "+f"(c[2]), "+f"(c[3])
        : "r"(a[0]), "r"(a[1]), "r"(a[2]), "r"(a[3]), "r"(b[0]), "r"(b[1]));
}

__global__ void __launch_bounds__(NT, 2)
gemm_f16_kernel(const float* __restrict__ bias, float* __restrict__ Y)
{
    extern __shared__ char smem[];
    const uint32_t smem_base = smem_u32(smem);
    const int tid  = threadIdx.x;
    const int warp = tid >> 5;
    const int lane = tid & 31;
    const int lg   = lane >> 2;
    const int lq   = lane & 3;
    const int wm   = (warp >> 1) * 32;   // 4 warps in M
    const int wn   = (warp & 1) * 64;    // 2 warps in N
    const int bm   = blockIdx.y * BM;
    const int bn   = blockIdx.x * BN;

    float c[2][8][4];
    #pragma unroll
    for (int mi = 0; mi < 2; ++mi)
        #pragma unroll
        for (int ni = 0; ni < 8; ++ni)
            #pragma unroll
            for (int j = 0; j < 4; ++j) c[mi][ni][j] = 0.0f;

    // per-thread load roles: 1024 16B chunks per operand tile, 4 per thread
    auto stage_load = [&](int st, int it) {
        const int k0 = it * BK;
        const uint32_t abase = smem_base + st * STAGE_BYTES;
        const uint32_t bbase = abase + A_BYTES;
        #pragma unroll
        for (int j = 0; j < 4; ++j) {
            int ch = tid + j * NT;           // 0..1023
            int row = ch >> 3, seg = ch & 7; // row, 16B segment
            const __half* sa = g_Xh + (size_t)(bm + row) * K_DIM + k0 + seg * 8;
            cp16(abase + sw128((uint32_t)(row * 128 + seg * 16)), sa);
            const __half* sb = g_Wh + (size_t)(bn + row) * K_DIM + k0 + seg * 8;
            cp16(bbase + sw128((uint32_t)(row * 128 + seg * 16)), sb);
        }
    };

    auto compute = [&](int st) {
        const uint32_t abase = smem_base + st * STAGE_BYTES;
        const uint32_t bbase = abase + A_BYTES;
        #pragma unroll
        for (int ks = 0; ks < 4; ++ks) {     // four k16 steps per BK=64
            uint32_t a[2][4], b[8][2];
            #pragma unroll
            for (int mi = 0; mi < 2; ++mi) {
                int row = wm + mi * 16 + (lane & 15);
                int colh = ks * 16 + ((lane >> 4) << 3);
                ldsm_x4(a[mi], abase + sw128((uint32_t)(row * 128 + colh * 2)));
            }
            #pragma unroll
            for (int nj = 0; nj < 4; ++nj) {
                int row = wn + nj * 16 + ((lane >> 4) << 3) + (lane & 7);
                int colh = ks * 16 + ((lane >> 3) & 1) * 8;
                uint32_t r[4];
                ldsm_x4(r, bbase + sw128((uint32_t)(row * 128 + colh * 2)));
                b[2 * nj][0] = r[0];     b[2 * nj][1] = r[1];
                b[2 * nj + 1][0] = r[2]; b[2 * nj + 1][1] = r[3];
            }
            #pragma unroll
            for (int mi = 0; mi < 2; ++mi)
                #pragma unroll
                for (int ni = 0; ni < 8; ++ni)
                    mma_f16(c[mi][ni], a[mi], b[ni]);
        }
    };

    // ---- prologue: stages 0,1 in flight ----
    stage_load(0, 0);
    asm volatile("cp.async.commit_group;\n");
    stage_load(1, 1);
    asm volatile("cp.async.commit_group;\n");

    for (int it = 0; it < NITER; ++it) {
        asm volatile("cp.async.wait_group 1;\n");   // stage `it` landed
        __syncthreads();                            // all warps done with stage (it-1)
        const int nit = it + 2;
        if (nit < NITER) stage_load(nit % STAGES, nit);
        asm volatile("cp.async.commit_group;\n");   // keep group count uniform
        compute(it % STAGES);
    }

    // ---- epilogue: bias + fp32 store ----
    #pragma unroll
    for (int ni = 0; ni < 8; ++ni) {
        int coln = bn + wn + ni * 8 + 2 * lq;
        float2 bv = *reinterpret_cast<const float2*>(bias + coln);
        #pragma unroll
        for (int mi = 0; mi < 2; ++mi) {
            int r = bm + wm + mi * 16 + lg;
            float2 v0 = make_float2(c[mi][ni][0] + bv.x, c[mi][ni][1] + bv.y);
            float2 v1 = make_float2(c[mi][ni][2] + bv.x, c[mi][ni][3] + bv.y);
            *reinterpret_cast<float2*>(Y + (size_t)r * N_DIM + coln) = v0;
            *reinterpret_cast<float2*>(Y + (size_t)(r + 8) * N_DIM + coln) = v1;
        }
    }
}

extern "C" void kernel_launch(void* const* d_in, const int* in_sizes, int n_in,
                              void* d_out, int out_size) {
    const float* X    = (const float*)d_in[0];
    const int*   Wq   = (const int*)d_in[1];
    const float* Wn   = (const float*)d_in[2];   // fp16 widened to fp32 by harness
    const float* bias = (const float*)d_in[3];
    float*       Y    = (float*)d_out;

    // prepass
    conv_x_kernel<<<(int)(((size_t)M_DIM * K_DIM / 8) / 256), 256>>>(X);
    dequant_w_kernel<<<(int)(((size_t)N_DIM * K_DIM / 16) / 256), 256>>>(Wq, Wn);

    // main GEMM
    cudaFuncSetAttribute(gemm_f16_kernel,
                         cudaFuncAttributeMaxDynamicSharedMemorySize, SMEM_TOTAL);
    dim3 grid(N_DIM / BN, M_DIM / BM);   // (32, 64) — N fastest: W stays L2-resident
    gemm_f16_kernel<<<grid, NT, SMEM_TOTAL>>>(bias, Y);
}

// round 10
// speedup vs baseline: 1.0019x; 1.0013x over previous
#include <cuda_runtime.h>
#include <cuda_fp16.h>
#include <cstdint>

// ============================================================
// Y[8192,4096] = X[8192,4096] @ dequant4(Wq,Wn)^T + bias
// Prepass: X f32->f16, W int4->f16.  Main: f16 GEMM (mma.sync
// m16n8k16, fp32 accum), cp.async 3-stage, SW128 swizzle.
// ============================================================
#define M_DIM 8192
#define N_DIM 4096
#define K_DIM 4096

__device__ __half g_Xh[(size_t)M_DIM * K_DIM];   // 64 MiB scratch
__device__ __half g_Wh[(size_t)N_DIM * K_DIM];   // 32 MiB scratch

// ---------------- prepass kernels ----------------
__global__ void __launch_bounds__(256)
conv_x_kernel(const float* __restrict__ X) {
    size_t i = ((size_t)blockIdx.x * 256 + threadIdx.x) * 8;
    float4 f0 = *reinterpret_cast<const float4*>(X + i);
    float4 f1 = *reinterpret_cast<const float4*>(X + i + 4);
    __half2 h[4];
    h[0] = __floats2half2_rn(f0.x, f0.y);
    h[1] = __floats2half2_rn(f0.z, f0.w);
    h[2] = __floats2half2_rn(f1.x, f1.y);
    h[3] = __floats2half2_rn(f1.z, f1.w);
    *reinterpret_cast<uint4*>(g_Xh + i) = *reinterpret_cast<const uint4*>(h);
}

__global__ void __launch_bounds__(256)
dequant_w_kernel(const int* __restrict__ Wq, const float* __restrict__ Wn) {
    size_t g = (size_t)blockIdx.x * 256 + threadIdx.x;   // group id, 1M groups
    const int4* gp = reinterpret_cast<const int4*>(Wq + g * 8);
    int4 w0 = gp[0], w1 = gp[1];
    float nf = Wn[g];
    float s = nf * (2.0f / 15.0f);
    int v[8] = {w0.x, w0.y, w0.z, w0.w, w1.x, w1.y, w1.z, w1.w};
    __half2 o[8];
    #pragma unroll
    for (int i = 0; i < 8; ++i) {
        float f0 = fmaf((float)(v[i] & 15),        s, -nf);  // low nibble = even k
        float f1 = fmaf((float)((v[i] >> 4) & 15), s, -nf);  // high nibble = odd k
        o[i] = __floats2half2_rn(f0, f1);
    }
    uint4* dst = reinterpret_cast<uint4*>(g_Wh + g * 16);
    dst[0] = reinterpret_cast<const uint4*>(o)[0];
    dst[1] = reinterpret_cast<const uint4*>(o)[1];
}

// ---------------- main GEMM ----------------
#define BM 128
#define BN 128
#define BK 64
#define NT 256
#define NITER (K_DIM / BK)            // 64
#define STAGES 3
#define A_BYTES (BM * BK * 2)         // 16384
#define B_BYTES (BN * BK * 2)         // 16384
#define STAGE_BYTES (A_BYTES + B_BYTES)
#define SMEM_TOTAL (STAGES * STAGE_BYTES)  // 98304

__device__ __forceinline__ uint32_t sw128(uint32_t off) {   // 128B rows
    return off ^ ((off >> 3) & 0x70);
}

__device__ __forceinline__ uint32_t smem_u32(const void* p) {
    uint32_t a;
    asm("{ .reg .u64 t; cvta.to.shared.u64 t, %1; cvt.u32.u64 %0, t; }" : "=r"(a) : "l"(p));
    return a;
}

__device__ __forceinline__ void cp16(uint32_t dst, const void* src) {
    asm volatile("cp.async.cg.shared.global [%0], [%1], 16;\n" :: "r"(dst), "l"(src));
}

__device__ __forceinline__ void ldsm_x4(uint32_t r[4], uint32_t addr) {
    asm volatile("ldmatrix.sync.aligned.m8n8.x4.shared.b16 {%0,%1,%2,%3}, [%4];"
                 : "=r"(r[0]), "=r"(r[1]), "=r"(r[2]), "=r"(r[3]) : "r"(addr));
}

__device__ __forceinline__ void mma_f16(float c[4], const uint32_t a[4], const uint32_t b[2]) {
    asm volatile(
        "mma.sync.aligned.m16n8k16.row.col.f32.f16.f16.f32 "
        "{%0,%1,%2,%3}, {%4,%5,%6,%7}, {%8,%9}, {%0,%1,%2,%3};\n"
        : "+f"(c[0]), "+f"(c[1]), "+f"(c[2]), "+f"(c[3])
        : "r"(a[0]), "r"(a[1]), "r"(a[2]), "r"(a[3]), "r"(b[0]), "r"(b[1]));
}

__global__ void __launch_bounds__(NT, 2)
gemm_f16_kernel(const float* __restrict__ bias, float* __restrict__ Y)
{
    extern __shared__ char smem[];
    const uint32_t smem_base = smem_u32(smem);
    const int tid  = threadIdx.x;
    const int warp = tid >> 5;
    const int lane = tid & 31;
    const int lg   = lane >> 2;
    const int lq   = lane & 3;
    const int wm   = (warp >> 1) * 32;   // 4 warps in M
    const int wn   = (warp & 1) * 64;    // 2 warps in N
    const int bm   = blockIdx.y * BM;
    const int bn   = blockIdx.x * BN;

    float c[2][8][4];
    #pragma unroll
    for (int mi = 0; mi < 2; ++mi)
        #pragma unroll
        for (int ni = 0; ni < 8; ++ni)
            #pragma unroll
            for (int j = 0; j < 4; ++j) c[mi][ni][j] = 0.0f;

    // per-thread load roles: 1024 16B chunks per operand tile, 4 per thread
    auto stage_load = [&](int st, int it) {
        const int k0 = it * BK;
        const uint32_t abase = smem_base + st * STAGE_BYTES;
        const uint32_t bbase = abase + A_BYTES;
        #pragma unroll
        for (int j = 0; j < 4; ++j) {
            int ch = tid + j * NT;           // 0..1023
            int row = ch >> 3, seg = ch & 7; // row, 16B segment
            const __half* sa = g_Xh + (size_t)(bm + row) * K_DIM + k0 + seg * 8;
            cp16(abase + sw128((uint32_t)(row * 128 + seg * 16)), sa);
            const __half* sb = g_Wh + (size_t)(bn + row) * K_DIM + k0 + seg * 8;
            cp16(bbase + sw128((uint32_t)(row * 128 + seg * 16)), sb);
        }
    };

    auto compute = [&](int st) {
        const uint32_t abase = smem_base + st * STAGE_BYTES;
        const uint32_t bbase = abase + A_BYTES;
        #pragma unroll
        for (int ks = 0; ks < 4; ++ks) {     // four k16 steps per BK=64
            uint32_t a[2][4], b[8][2];
            #pragma unroll
            for (int mi = 0; mi < 2; ++mi) {
                int row = wm + mi * 16 + (lane & 15);
                int colh = ks * 16 + ((lane >> 4) << 3);
                ldsm_x4(a[mi], abase + sw128((uint32_t)(row * 128 + colh * 2)));
            }
            #pragma unroll
            for (int nj = 0; nj < 4; ++nj) {
                int row = wn + nj * 16 + ((lane >> 4) << 3) + (lane & 7);
                int colh = ks * 16 + ((lane >> 3) & 1) * 8;
                uint32_t r[4];
                ldsm_x4(r, bbase + sw128((uint32_t)(row * 128 + colh * 2)));
                b[2 * nj][0] = r[0];     b[2 * nj][1] = r[1];
                b[2 * nj + 1][0] = r[2]; b[2 * nj + 1][1] = r[3];
            }
            #pragma unroll
            for (int mi = 0; mi < 2; ++mi)
                #pragma unroll
                for (int ni = 0; ni < 8; ++ni)
                    mma_f16(c[mi][ni], a[mi], b[ni]);
        }
    };

    // ---- prologue: stages 0,1 in flight ----
    stage_load(0, 0);
    asm volatile("cp.async.commit_group;\n");
    stage_load(1, 1);
    asm volatile("cp.async.commit_group;\n");

    for (int it = 0; it < NITER; ++it) {
        asm volatile("cp.async.wait_group 1;\n");   // stage `it` landed
        __syncthreads();                            // all warps done with stage (it-1)
        const int nit = it + 2;
        if (nit < NITER) stage_load(nit % STAGES, nit);
        asm volatile("cp.async.commit_group;\n");   // keep group count uniform
        compute(it % STAGES);
    }

    // ---- epilogue: bias + fp32 store ----
    #pragma unroll
    for (int ni = 0; ni < 8; ++ni) {
        int coln = bn + wn + ni * 8 + 2 * lq;
        float2 bv = *reinterpret_cast<const float2*>(bias + coln);
        #pragma unroll
        for (int mi = 0; mi < 2; ++mi) {
            int r = bm + wm + mi * 16 + lg;
            float2 v0 = make_float2(c[mi][ni][0] + bv.x, c[mi][ni][1] + bv.y);
            float2 v1 = make_float2(c[mi][ni][2] + bv.x, c[mi][ni][3] + bv.y);
            *reinterpret_cast<float2*>(Y + (size_t)r * N_DIM + coln) = v0;
            *reinterpret_cast<float2*>(Y + (size_t)(r + 8) * N_DIM + coln) = v1;
        }
    }
}

extern "C" void kernel_launch(void* const* d_in, const int* in_sizes, int n_in,
                              void* d_out, int out_size) {
    const float* X    = (const float*)d_in[0];
    const int*   Wq   = (const int*)d_in[1];
    const float* Wn   = (const float*)d_in[2];   // fp16 widened to fp32 by harness
    const float* bias = (const float*)d_in[3];
    float*       Y    = (float*)d_out;

    // prepass
    conv_x_kernel<<<(int)(((size_t)M_DIM * K_DIM / 8) / 256), 256>>>(X);
    dequant_w_kernel<<<(int)(((size_t)N_DIM * K_DIM / 16) / 256), 256>>>(Wq, Wn);

    // main GEMM
    cudaFuncSetAttribute(gemm_f16_kernel,
                         cudaFuncAttributeMaxDynamicSharedMemorySize, SMEM_TOTAL);
    dim3 grid(N_DIM / BN, M_DIM / BM);   // (32, 64) — N fastest: W stays L2-resident
    gemm_f16_kernel<<<grid, NT, SMEM_TOTAL>>>(bias, Y);
}